// round 16
// baseline (speedup 1.0000x reference)
#include <cuda_runtime.h>
#include <cuda_fp16.h>

#define Sd 48
#define SP (Sd*Sd*Sd)      // 110592
#define Bb 2
#define Cc 128
#define NVx (Bb*SP)        // 221184

// ---------------- mma / ldmatrix / cp.async helpers -------------------------
__device__ __forceinline__ void mma_f16(float* d, const unsigned* a, const unsigned* b) {
    asm volatile(
        "mma.sync.aligned.m16n8k16.row.col.f32.f16.f16.f32 "
        "{%0,%1,%2,%3},{%4,%5,%6,%7},{%8,%9},{%0,%1,%2,%3};"
        : "+f"(d[0]), "+f"(d[1]), "+f"(d[2]), "+f"(d[3])
        : "r"(a[0]), "r"(a[1]), "r"(a[2]), "r"(a[3]), "r"(b[0]), "r"(b[1]));
}
__device__ __forceinline__ unsigned smaddr(const void* p) {
    unsigned a;
    asm("{ .reg .u64 t; cvta.to.shared.u64 t, %1; cvt.u32.u64 %0, t; }" : "=r"(a) : "l"(p));
    return a;
}
__device__ __forceinline__ void ldsm_x4(unsigned* r, unsigned a) {
    asm volatile("ldmatrix.sync.aligned.m8n8.x4.shared.b16 {%0,%1,%2,%3},[%4];"
        : "=r"(r[0]), "=r"(r[1]), "=r"(r[2]), "=r"(r[3]) : "r"(a));
}
__device__ __forceinline__ void ldsm_x2(unsigned* r, unsigned a) {
    asm volatile("ldmatrix.sync.aligned.m8n8.x2.shared.b16 {%0,%1},[%2];"
        : "=r"(r[0]), "=r"(r[1]) : "r"(a));
}
__device__ __forceinline__ void ldsm_x4_t(unsigned* r, unsigned a) {
    asm volatile("ldmatrix.sync.aligned.m8n8.x4.trans.shared.b16 {%0,%1,%2,%3},[%4];"
        : "=r"(r[0]), "=r"(r[1]), "=r"(r[2]), "=r"(r[3]) : "r"(a));
}
__device__ __forceinline__ float2 h2f2(unsigned u) {
    __half2 h = *reinterpret_cast<__half2*>(&u);
    return __half22float2(h);
}
__device__ __forceinline__ void cpa16(void* smem, const void* gmem) {
    unsigned s = smaddr(smem);
    asm volatile("cp.async.cg.shared.global [%0], [%1], 16;" :: "r"(s), "l"(gmem));
}
#define CPA_COMMIT() asm volatile("cp.async.commit_group;")
#define CPA_WAIT0()  asm volatile("cp.async.wait_group 0;")
#define CPA_WAIT1()  asm volatile("cp.async.wait_group 1;")

// ---------------- scratch --------------------------------------------------
__device__ __half g_hh[(size_t)Bb*Cc*SP];      // residual stream h (fp16)
__device__ __half g_T[(size_t)NVx*64];
__device__ __half g_P[(size_t)NVx*64];
__device__ __half g_G[(size_t)NVx*64];
__device__ __half g_Yd[(size_t)NVx*64];        // D-dir partial, vox-major
__device__ __half g_Yh[(size_t)NVx*64];        // H-dir partial, vox-major
__device__ float g_md[NVx]; __device__ float g_sd[NVx];
__device__ float g_mh[NVx]; __device__ float g_sh[NVx];
__device__ __half g_cross[(size_t)Bb*Cc*SP];   // channel-first, fp16
__device__ __half g_WT16[192*128];             // fused theta/phi/G weights [m][k]
__device__ __half g_rwT16[128*64];             // r_w [m=ch][k=g]
__device__ float g_gnsum[Bb*32]; __device__ float g_gnss[Bb*32];
__device__ float g_bnsum[Cc];    __device__ float g_bnss[Cc];

// ---------------- one-time weight convert + BN-stat zero --------------------
__global__ __launch_bounds__(256) void wtrans_kernel(
    const float* __restrict__ tw, const float* __restrict__ pw,
    const float* __restrict__ gw, const float* __restrict__ rw)
{
    int idx = blockIdx.x*256 + threadIdx.x;
    if (idx < 192*128) {
        float v;
        if (idx < 64*128)       v = tw[idx];
        else if (idx < 128*128) v = pw[idx - 64*128];
        else                    v = gw[idx - 128*128];
        g_WT16[idx] = __float2half(v);
    }
    if (idx < 128*64) g_rwT16[idx] = __float2half(rw[idx]);
    if (idx < Cc) { g_bnsum[idx] = 0.f; g_bnss[idx] = 0.f; }
}

// ---------------- projection (fp16 mma): [192m x 64n] tile, K=128 ----------
__global__ __launch_bounds__(256) void proj_kernel(
    int layer, const float* __restrict__ x,
    const float* __restrict__ tb, const float* __restrict__ pb,
    const float* __restrict__ gb)
{
    __shared__ __align__(16) __half SM[192*40*2 + 32*72];
    __half* As0 = SM;                  // [192][40]
    __half* As1 = SM + 192*40;
    __half* Bs  = SM + 192*40*2;       // [32][72]
    __half* U   = SM;                  // staging [vox 64][m 200] (aliases As)
    const int b = blockIdx.y, n0 = blockIdx.x*64, tid = threadIdx.x;
    if (blockIdx.x == 0 && blockIdx.y == 0 && tid < Bb*32) {
        g_gnsum[tid] = 0.f; g_gnss[tid] = 0.f;
    }
    const int warp = tid >> 5, lane = tid & 31;
    const int grp = lane >> 2, tig = lane & 3;
    const int m_base = (warp >> 1) * 48, n_base = (warp & 1) * 32;

    float acc[3][4][4];
    #pragma unroll
    for (int mt = 0; mt < 3; mt++)
        #pragma unroll
        for (int nt = 0; nt < 4; nt++)
            #pragma unroll
            for (int q = 0; q < 4; q++) acc[mt][nt][q] = 0.f;

    const unsigned A0addr = smaddr(&As0[(m_base + (lane & 15))*40 + (lane >> 4)*8]);
    const unsigned Baddr  = smaddr(&Bs[((lane & 7) + ((lane >> 3) & 1)*8)*72
                                       + n_base + (lane >> 4)*8]);

    #pragma unroll
    for (int it = 0; it < 3; it++) {
        int idx = it*256 + tid;
        int m = idx >> 2, kp = (idx & 3)*8;
        cpa16(&As0[m*40 + kp], &g_WT16[m*128 + kp]);
    }
    CPA_COMMIT();

    for (int k0 = 0; k0 < 128; k0 += 32) {
        const int buf = (k0 >> 5) & 1;
        {
            int kk = tid >> 3, n8 = (tid & 7)*8;
            size_t off = (size_t)(b*Cc + k0 + kk)*SP + n0 + n8;
            if (layer) {
                *(uint4*)&Bs[kk*72 + n8] = *(const uint4*)&g_hh[off];
            } else {
                const float* s = &x[off];
                float4 v0 = *(const float4*)s, v1 = *(const float4*)(s + 4);
                __half2 h0 = __floats2half2_rn(v0.x, v0.y);
                __half2 h1 = __floats2half2_rn(v0.z, v0.w);
                __half2 h2 = __floats2half2_rn(v1.x, v1.y);
                __half2 h3 = __floats2half2_rn(v1.z, v1.w);
                uint4 pk;
                pk.x = *(unsigned*)&h0; pk.y = *(unsigned*)&h1;
                pk.z = *(unsigned*)&h2; pk.w = *(unsigned*)&h3;
                *(uint4*)&Bs[kk*72 + n8] = pk;
            }
        }
        CPA_WAIT0();
        __syncthreads();
        if (k0 + 32 < 128) {
            __half* Anext = buf ? As0 : As1;
            #pragma unroll
            for (int it = 0; it < 3; it++) {
                int idx = it*256 + tid;
                int m = idx >> 2, kp = (idx & 3)*8;
                cpa16(&Anext[m*40 + kp], &g_WT16[m*128 + k0 + 32 + kp]);
            }
            CPA_COMMIT();
        }
        const unsigned Aaddr = A0addr + (buf ? 192*40*2 : 0);
        #pragma unroll
        for (int kc = 0; kc < 2; kc++) {
            unsigned bv0[4], bv1[4];
            ldsm_x4_t(bv0, Baddr + kc*16*144);
            ldsm_x4_t(bv1, Baddr + kc*16*144 + 32);
            #pragma unroll
            for (int mt = 0; mt < 3; mt++) {
                unsigned af[4];
                ldsm_x4(af, Aaddr + mt*16*80 + kc*32);
                mma_f16(acc[mt][0], af, bv0);
                mma_f16(acc[mt][1], af, bv0 + 2);
                mma_f16(acc[mt][2], af, bv1);
                mma_f16(acc[mt][3], af, bv1 + 2);
            }
        }
        __syncthreads();
    }

    #pragma unroll
    for (int mt = 0; mt < 3; mt++) {
        #pragma unroll
        for (int rr = 0; rr < 2; rr++) {
            const int r = m_base + mt*16 + rr*8 + grp;
            const float bv = (r < 64) ? tb[r] : (r < 128 ? pb[r-64] : gb[r-128]);
            #pragma unroll
            for (int nt = 0; nt < 4; nt++) {
                const int c = n_base + nt*8 + tig*2;
                U[ c   *200 + r] = __float2half(acc[mt][nt][rr*2 + 0] + bv);
                U[(c+1)*200 + r] = __float2half(acc[mt][nt][rr*2 + 1] + bv);
            }
        }
    }
    __syncthreads();
    #pragma unroll
    for (int it = 0; it < 6; it++) {
        int idx = it*256 + tid;
        int seg = idx >> 9;
        int rem = idx & 511;
        int vox = rem >> 3, ch = rem & 7;
        __half* dst = (seg == 0) ? g_T : ((seg == 1) ? g_P : g_G);
        uint4 val = *(const uint4*)&U[vox*200 + seg*64 + ch*8];
        *(uint4*)&dst[((size_t)b*SP + n0 + vox)*64 + ch*8] = val;
    }
}

// ---------------- merged D/H attention (blockIdx.y = direction 0/1) --------
__global__ __launch_bounds__(192) void attn01_kernel() {
    __shared__ __half Tl[48*72];
    __shared__ __half Pl[48*72];
    __shared__ __half Gl[48*72];
    __shared__ __half Sh[48*72];

    const int DIR = blockIdx.y;
    const int pid = blockIdx.x;
    const int b = pid / (Sd*Sd);
    const int rr = pid % (Sd*Sd);
    const int u = rr / Sd, v = rr % Sd;
    size_t base; int stride;
    if (DIR == 0) { base = (size_t)b*SP + u*Sd + v;    stride = Sd*Sd; }
    else          { base = (size_t)b*SP + u*Sd*Sd + v; stride = Sd;    }
    const int tid = threadIdx.x;
    const int warp = tid >> 5, lane = tid & 31;
    const int grp = lane >> 2, tig = lane & 3;

    for (int l = tid; l < 48*8; l += 192) {
        int i = l >> 3, k8 = (l & 7) * 8;
        size_t o = (base + (size_t)i*stride)*64 + k8;
        cpa16(&Gl[i*72 + k8], &g_G[o]);
        *(uint4*)&Tl[i*72 + k8] = *(const uint4*)&g_T[o];
        *(uint4*)&Pl[i*72 + k8] = *(const uint4*)&g_P[o];
    }
    CPA_COMMIT();
    __syncthreads();

    const int mrow0 = (warp >> 1) * 16;
    const int mr = mrow0 + grp;
    const int nhalf = (warp & 1) * 24;
    const int ncol0 = (warp & 1) * 32;

    const unsigned Ta = smaddr(&Tl[(mrow0 + (lane & 15))*72 + (lane >> 4)*8]);
    const unsigned Pa = smaddr(&Pl[(nhalf + (lane & 7))*72 + ((lane >> 3) & 1)*8]);
    const unsigned Ga = smaddr(&Gl[((lane & 7) + ((lane >> 3) & 1)*8)*72
                                   + ncol0 + (lane >> 4)*8]);

    float sacc[3][4];
    #pragma unroll
    for (int nt = 0; nt < 3; nt++)
        #pragma unroll
        for (int q = 0; q < 4; q++) sacc[nt][q] = 0.f;
    #pragma unroll
    for (int kc = 0; kc < 4; kc++) {
        unsigned af[4];
        ldsm_x4(af, Ta + kc*32);
        #pragma unroll
        for (int nt = 0; nt < 3; nt++) {
            unsigned bf[2];
            ldsm_x2(bf, Pa + nt*8*144 + kc*32);
            mma_f16(sacc[nt], af, bf);
        }
    }

    #pragma unroll
    for (int nt = 0; nt < 3; nt++) {
        const int j0 = nhalf + nt*8 + tig*2;
        float c0 = sacc[nt][0], c1 = sacc[nt][1], c2 = sacc[nt][2], c3 = sacc[nt][3];
        if (DIR != 0) {
            if (mr     == j0    ) c0 = -1e30f;
            if (mr     == j0 + 1) c1 = -1e30f;
            if (mr + 8 == j0    ) c2 = -1e30f;
            if (mr + 8 == j0 + 1) c3 = -1e30f;
        }
        *(__half2*)&Sh[ mr     *72 + j0] = __floats2half2_rn(c0, c1);
        *(__half2*)&Sh[(mr + 8)*72 + j0] = __floats2half2_rn(c2, c3);
    }
    __syncthreads();

    {
        const int r = tid >> 2, q = tid & 3;
        float vals[12];
        float mx = -3.0e38f;
        #pragma unroll
        for (int j = 0; j < 12; j += 2) {
            float2 vv = h2f2(*(const unsigned*)&Sh[r*72 + q*12 + j]);
            vals[j] = vv.x; vals[j+1] = vv.y;
            mx = fmaxf(mx, fmaxf(vv.x, vv.y));
        }
        mx = fmaxf(mx, __shfl_xor_sync(0xffffffffu, mx, 1));
        mx = fmaxf(mx, __shfl_xor_sync(0xffffffffu, mx, 2));
        float sm = 0.f;
        #pragma unroll
        for (int j = 0; j < 12; j++) {
            float e = __expf(vals[j] - mx);
            sm += e;
            Tl[r*72 + q*12 + j] = __float2half(e);
        }
        sm += __shfl_xor_sync(0xffffffffu, sm, 1);
        sm += __shfl_xor_sync(0xffffffffu, sm, 2);
        if (q == 0) {
            size_t vx = base + (size_t)r*stride;
            if (DIR == 0) { g_md[vx] = mx; g_sd[vx] = sm; }
            else          { g_mh[vx] = mx; g_sh[vx] = sm; }
        }
    }
    CPA_WAIT0();
    __syncthreads();

    float yacc[4][4];
    #pragma unroll
    for (int nt = 0; nt < 4; nt++)
        #pragma unroll
        for (int q = 0; q < 4; q++) yacc[nt][q] = 0.f;
    #pragma unroll
    for (int kc = 0; kc < 3; kc++) {
        unsigned af[4];
        ldsm_x4(af, Ta + kc*32);
        #pragma unroll
        for (int pair = 0; pair < 2; pair++) {
            unsigned bv[4];
            ldsm_x4_t(bv, Ga + kc*16*144 + pair*32);
            mma_f16(yacc[pair*2],     af, bv);
            mma_f16(yacc[pair*2 + 1], af, bv + 2);
        }
    }

    __half* Yout = (DIR == 0) ? g_Yd : g_Yh;
    #pragma unroll
    for (int nt = 0; nt < 4; nt++) {
        const int c = ncol0 + nt*8 + tig*2;
        *(__half2*)&Yout[(base + (size_t)mr*stride)*64 + c] =
            __floats2half2_rn(yacc[nt][0], yacc[nt][1]);
        *(__half2*)&Yout[(base + (size_t)(mr + 8)*stride)*64 + c] =
            __floats2half2_rn(yacc[nt][2], yacc[nt][3]);
    }
}

// ---------------- W-attention + combine + FUSED cross GEMM ------------------
// SM layout: Tl | Pl | Gl | Sh | Rs.  After AV+combine, Sh holds combined
// Y[48vox][64g]; Rs holds rw[128][64]; cross D = rw @ Y^T done in-block;
// Tl+Pl reused as D staging [128ch][48vox] for coalesced g_cross stores.
__global__ __launch_bounds__(192) void attn2_kernel(const float* __restrict__ rb) {
    __shared__ __align__(16) __half SM[48*72*4 + 128*72];
    __half* Tl = SM;
    __half* Pl = SM + 48*72;
    __half* Gl = SM + 48*72*2;
    __half* Sh = SM + 48*72*3;
    __half* Rs = SM + 48*72*4;       // rw [128][64], pitch 72
    __half* Dst = SM;                // D staging [128][48] (aliases Tl+Pl)
    __shared__ float rmS[48], rsS[48];
    __shared__ float gsum[32], gss[32];

    const int pid = blockIdx.x;
    const int b = pid / (Sd*Sd);
    const int rr = pid % (Sd*Sd);
    const int u = rr / Sd, v = rr % Sd;
    const size_t base = (size_t)b*SP + u*Sd*Sd + v*Sd;   // stride 1
    const size_t sp0 = base - (size_t)b*SP;
    const int tid = threadIdx.x;
    const int warp = tid >> 5, lane = tid & 31;
    const int grp = lane >> 2, tig = lane & 3;
    if (tid < 32) { gsum[tid] = 0.f; gss[tid] = 0.f; }

    // G async (group 0 latest before rw), rw async (last group)
    for (int l = tid; l < 48*8; l += 192) {
        int i = l >> 3, k8 = (l & 7) * 8;
        size_t o = (base + (size_t)i)*64 + k8;
        cpa16(&Gl[i*72 + k8], &g_G[o]);
        *(uint4*)&Tl[i*72 + k8] = *(const uint4*)&g_T[o];
        *(uint4*)&Pl[i*72 + k8] = *(const uint4*)&g_P[o];
    }
    CPA_COMMIT();
    #pragma unroll
    for (int it = 0; it < 6; it++) {
        int idx = it*192 + tid;              // 0..1151, need 1024
        if (idx < 1024) {
            int m = idx >> 3, kp = (idx & 7)*8;
            cpa16(&Rs[m*72 + kp], &g_rwT16[m*64 + kp]);
        }
    }
    CPA_COMMIT();
    __syncthreads();

    const int mrow0 = (warp >> 1) * 16;
    const int mr = mrow0 + grp;
    const int nhalf = (warp & 1) * 24;
    const int ncol0 = (warp & 1) * 32;

    const unsigned Ta = smaddr(&Tl[(mrow0 + (lane & 15))*72 + (lane >> 4)*8]);
    const unsigned Pa = smaddr(&Pl[(nhalf + (lane & 7))*72 + ((lane >> 3) & 1)*8]);
    const unsigned Ga = smaddr(&Gl[((lane & 7) + ((lane >> 3) & 1)*8)*72
                                   + ncol0 + (lane >> 4)*8]);

    // ---- scores ----
    float sacc[3][4];
    #pragma unroll
    for (int nt = 0; nt < 3; nt++)
        #pragma unroll
        for (int q = 0; q < 4; q++) sacc[nt][q] = 0.f;
    #pragma unroll
    for (int kc = 0; kc < 4; kc++) {
        unsigned af[4];
        ldsm_x4(af, Ta + kc*32);
        #pragma unroll
        for (int nt = 0; nt < 3; nt++) {
            unsigned bf[2];
            ldsm_x2(bf, Pa + nt*8*144 + kc*32);
            mma_f16(sacc[nt], af, bf);
        }
    }
    #pragma unroll
    for (int nt = 0; nt < 3; nt++) {
        const int j0 = nhalf + nt*8 + tig*2;
        float c0 = sacc[nt][0], c1 = sacc[nt][1], c2 = sacc[nt][2], c3 = sacc[nt][3];
        if (mr     == j0    ) c0 = -1e30f;
        if (mr     == j0 + 1) c1 = -1e30f;
        if (mr + 8 == j0    ) c2 = -1e30f;
        if (mr + 8 == j0 + 1) c3 = -1e30f;
        *(__half2*)&Sh[ mr     *72 + j0] = __floats2half2_rn(c0, c1);
        *(__half2*)&Sh[(mr + 8)*72 + j0] = __floats2half2_rn(c2, c3);
    }
    __syncthreads();

    // ---- softmax (probs into Tl) ----
    {
        const int r = tid >> 2, q = tid & 3;
        float vals[12];
        float mx = -3.0e38f;
        #pragma unroll
        for (int j = 0; j < 12; j += 2) {
            float2 vv = h2f2(*(const unsigned*)&Sh[r*72 + q*12 + j]);
            vals[j] = vv.x; vals[j+1] = vv.y;
            mx = fmaxf(mx, fmaxf(vv.x, vv.y));
        }
        mx = fmaxf(mx, __shfl_xor_sync(0xffffffffu, mx, 1));
        mx = fmaxf(mx, __shfl_xor_sync(0xffffffffu, mx, 2));
        float sm = 0.f;
        #pragma unroll
        for (int j = 0; j < 12; j++) {
            float e = __expf(vals[j] - mx);
            sm += e;
            Tl[r*72 + q*12 + j] = __float2half(e);
        }
        sm += __shfl_xor_sync(0xffffffffu, sm, 1);
        sm += __shfl_xor_sync(0xffffffffu, sm, 2);
        if (q == 0) { rmS[r] = mx; rsS[r] = sm; }
    }
    CPA_WAIT1();             // G done (rw may still be in flight)
    __syncthreads();

    // ---- AV ----
    float yacc[4][4];
    #pragma unroll
    for (int nt = 0; nt < 4; nt++)
        #pragma unroll
        for (int q = 0; q < 4; q++) yacc[nt][q] = 0.f;
    #pragma unroll
    for (int kc = 0; kc < 3; kc++) {
        unsigned af[4];
        ldsm_x4(af, Ta + kc*32);
        #pragma unroll
        for (int pair = 0; pair < 2; pair++) {
            unsigned bv[4];
            ldsm_x4_t(bv, Ga + kc*16*144 + pair*32);
            mma_f16(yacc[pair*2],     af, bv);
            mma_f16(yacc[pair*2 + 1], af, bv + 2);
        }
    }
    // stage W-partial Y into Sh
    #pragma unroll
    for (int nt = 0; nt < 4; nt++) {
        const int c = ncol0 + nt*8 + tig*2;
        *(__half2*)&Sh[ mr     *72 + c] = __floats2half2_rn(yacc[nt][0], yacc[nt][1]);
        *(__half2*)&Sh[(mr + 8)*72 + c] = __floats2half2_rn(yacc[nt][2], yacc[nt][3]);
    }
    __syncthreads();

    // ---- 3-way combine: Sh <- combined Y (vox-major) ----
    {
        const int ip = tid >> 3;
        const int g0 = (tid & 7) * 8;
        const int i0 = ip*2, i1 = i0 + 1;
        const size_t vox0 = base + i0, vox1 = base + i1;

        float md0 = g_md[vox0], sd0 = g_sd[vox0];
        float mh0 = g_mh[vox0], sh0 = g_sh[vox0];
        float mw0 = rmS[i0],    sw0 = rsS[i0];
        float m0  = fmaxf(md0, fmaxf(mh0, mw0));
        float wd0 = __expf(md0 - m0), wh0 = __expf(mh0 - m0), ww0 = __expf(mw0 - m0);
        float iv0 = 1.0f / (sd0*wd0 + sh0*wh0 + sw0*ww0);
        wd0 *= iv0; wh0 *= iv0; ww0 *= iv0;

        float md1 = g_md[vox1], sd1 = g_sd[vox1];
        float mh1 = g_mh[vox1], sh1 = g_sh[vox1];
        float mw1 = rmS[i1],    sw1 = rsS[i1];
        float m1  = fmaxf(md1, fmaxf(mh1, mw1));
        float wd1 = __expf(md1 - m1), wh1 = __expf(mh1 - m1), ww1 = __expf(mw1 - m1);
        float iv1 = 1.0f / (sd1*wd1 + sh1*wh1 + sw1*ww1);
        wd1 *= iv1; wh1 *= iv1; ww1 *= iv1;

        uint4 a0u = *(const uint4*)&g_Yd[vox0*64 + g0];
        uint4 a1u = *(const uint4*)&g_Yd[vox1*64 + g0];
        uint4 h0u = *(const uint4*)&g_Yh[vox0*64 + g0];
        uint4 h1u = *(const uint4*)&g_Yh[vox1*64 + g0];
        uint4 y0u = *(const uint4*)&Sh[i0*72 + g0];
        uint4 y1u = *(const uint4*)&Sh[i1*72 + g0];
        const unsigned* a0 = (const unsigned*)&a0u;
        const unsigned* a1 = (const unsigned*)&a1u;
        const unsigned* h0 = (const unsigned*)&h0u;
        const unsigned* h1 = (const unsigned*)&h1u;
        const unsigned* y0 = (const unsigned*)&y0u;
        const unsigned* y1 = (const unsigned*)&y1u;

        #pragma unroll
        for (int q = 0; q < 4; q++) {
            float2 av0 = h2f2(a0[q]), hv0 = h2f2(h0[q]), yv0 = h2f2(y0[q]);
            float2 av1 = h2f2(a1[q]), hv1 = h2f2(h1[q]), yv1 = h2f2(y1[q]);
            int g = g0 + q*2;
            *(__half2*)&Sh[i0*72 + g] = __floats2half2_rn(
                av0.x*wd0 + hv0.x*wh0 + yv0.x*ww0,
                av0.y*wd0 + hv0.y*wh0 + yv0.y*ww0);
            *(__half2*)&Sh[i1*72 + g] = __floats2half2_rn(
                av1.x*wd1 + hv1.x*wh1 + yv1.x*ww1,
                av1.y*wd1 + hv1.y*wh1 + yv1.y*ww1);
        }
    }
    CPA_WAIT0();             // rw tile ready
    __syncthreads();

    // ---- fused cross: D[128ch, 48vox] = rw[128,64] @ Y[48,64]^T ----
    // warp w: n-tile = w (vox w*8..w*8+7); loop 8 m16 tiles.
    const unsigned Ra = smaddr(&Rs[(lane & 15)*72 + (lane >> 4)*8]);
    const unsigned Ya = smaddr(&Sh[(warp*8 + (lane & 7))*72 + ((lane >> 3) & 1)*8]);
    float dacc[8][4];
    #pragma unroll
    for (int mt = 0; mt < 8; mt++)
        #pragma unroll
        for (int q = 0; q < 4; q++) dacc[mt][q] = 0.f;
    #pragma unroll
    for (int kc = 0; kc < 4; kc++) {
        unsigned bf[2];
        ldsm_x2(bf, Ya + kc*32);
        #pragma unroll
        for (int mt = 0; mt < 8; mt++) {
            unsigned af[4];
            ldsm_x4(af, Ra + mt*16*144 + kc*32);
            mma_f16(dacc[mt], af, bf);
        }
    }
    __syncthreads();     // probs/P reads done (Tl/Pl now dead) -> Dst staging

    // ---- bias + GN partial sums + stage D[ch][48] into Dst ----
    #pragma unroll
    for (int mt = 0; mt < 8; mt++) {
        #pragma unroll
        for (int rq = 0; rq < 2; rq++) {
            const int ch = mt*16 + rq*8 + grp;
            const float bv = rb[ch];
            const int c = warp*8 + tig*2;
            float v0 = dacc[mt][rq*2 + 0] + bv;
            float v1 = dacc[mt][rq*2 + 1] + bv;
            *(__half2*)&Dst[ch*48 + c] = __floats2half2_rn(v0, v1);
            float ps = v0 + v1, pss = v0*v0 + v1*v1;
            ps  += __shfl_xor_sync(0xffffffffu, ps, 1);
            ps  += __shfl_xor_sync(0xffffffffu, ps, 2);
            pss += __shfl_xor_sync(0xffffffffu, pss, 1);
            pss += __shfl_xor_sync(0xffffffffu, pss, 2);
            if (tig == 0) {
                atomicAdd(&gsum[ch >> 2], ps);
                atomicAdd(&gss [ch >> 2], pss);
            }
        }
    }
    __syncthreads();

    // ---- coalesced g_cross row stores (96B per channel row) ----
    #pragma unroll
    for (int it = 0; it < 4; it++) {
        int idx = it*192 + tid;               // 0..767
        int r = idx / 6, j = idx % 6;
        *(uint4*)&g_cross[((size_t)b*Cc + r)*SP + sp0 + j*8] =
            *(const uint4*)&Dst[r*48 + j*8];
    }
    if (tid < 32) {
        atomicAdd(&g_gnsum[b*32 + tid], gsum[tid]);
        atomicAdd(&g_gnss [b*32 + tid], gss[tid]);
    }
}

// ---------------- GroupNorm + residual (streaming, channel-first) ----------
__global__ __launch_bounds__(256) void gnres_kernel(
    int layer, const float* __restrict__ x,
    const float* __restrict__ gnw, const float* __restrict__ gnb,
    int accum_bn)
{
    const int c = blockIdx.y, b = blockIdx.z, chunk = blockIdx.x;
    const size_t base = ((size_t)(b*Cc + c))*SP + (size_t)chunk*(SP/4);
    const int g = c >> 2;
    const float invN = 1.0f / (4.0f * SP);
    float mu  = g_gnsum[b*32 + g] * invN;
    float var = g_gnss[b*32 + g] * invN - mu*mu;
    float rstd = rsqrtf(var + 1e-5f);
    float w = gnw[c], bias = gnb[c];
    float s = 0.f, ss = 0.f;
    for (int j = 0; j < 27; j++) {
        size_t o = base + (size_t)j*1024 + threadIdx.x*4;
        uint2 ch = *(const uint2*)&g_cross[o];
        float2 c01 = h2f2(ch.x), c23 = h2f2(ch.y);
        float4 rv;
        if (layer) {
            uint2 hv = *(const uint2*)&g_hh[o];
            float2 r01 = h2f2(hv.x), r23 = h2f2(hv.y);
            rv.x = r01.x; rv.y = r01.y; rv.z = r23.x; rv.w = r23.y;
        } else {
            rv = *(const float4*)&x[o];
        }
        float4 h;
        h.x = rv.x + (c01.x - mu)*rstd*w + bias;
        h.y = rv.y + (c01.y - mu)*rstd*w + bias;
        h.z = rv.z + (c23.x - mu)*rstd*w + bias;
        h.w = rv.w + (c23.y - mu)*rstd*w + bias;
        uint2 hw;
        __half2 w0 = __floats2half2_rn(h.x, h.y);
        __half2 w1 = __floats2half2_rn(h.z, h.w);
        hw.x = *(unsigned*)&w0; hw.y = *(unsigned*)&w1;
        *(uint2*)&g_hh[o] = hw;
        if (accum_bn) {
            s  += h.x + h.y + h.z + h.w;
            ss += h.x*h.x + h.y*h.y + h.z*h.z + h.w*h.w;
        }
    }
    if (accum_bn) {
        #pragma unroll
        for (int o = 16; o > 0; o >>= 1) {
            s  += __shfl_xor_sync(0xffffffffu, s,  o);
            ss += __shfl_xor_sync(0xffffffffu, ss, o);
        }
        __shared__ float ws[8], wss[8];
        int wid = threadIdx.x >> 5, lane = threadIdx.x & 31;
        if (lane == 0) { ws[wid] = s; wss[wid] = ss; }
        __syncthreads();
        if (threadIdx.x == 0) {
            float ts = 0.f, tss = 0.f;
            #pragma unroll
            for (int k = 0; k < 8; k++) { ts += ws[k]; tss += wss[k]; }
            atomicAdd(&g_bnsum[c], ts);
            atomicAdd(&g_bnss[c],  tss);
        }
    }
}

// ---------------- BatchNorm apply + ReLU ------------------------------------
__global__ __launch_bounds__(256) void bnapply_kernel(
    const float* __restrict__ bw, const float* __restrict__ bb, float* __restrict__ out)
{
    size_t i4 = (size_t)blockIdx.x*256 + threadIdx.x;
    if (i4 >= (size_t)Bb*Cc*SP/4) return;
    size_t i = i4 * 4;
    int c = (int)((i / SP) & 127);
    const float invN = 1.0f / ((float)Bb * SP);
    float mu  = g_bnsum[c] * invN;
    float var = g_bnss[c] * invN - mu*mu;
    float rstd = rsqrtf(var + 1e-5f);
    float wv = bw[c], bv = bb[c];
    uint2 hv = *(const uint2*)&g_hh[i];
    float2 v01 = h2f2(hv.x), v23 = h2f2(hv.y);
    float4 v;
    v.x = fmaxf((v01.x - mu)*rstd*wv + bv, 0.f);
    v.y = fmaxf((v01.y - mu)*rstd*wv + bv, 0.f);
    v.z = fmaxf((v23.x - mu)*rstd*wv + bv, 0.f);
    v.w = fmaxf((v23.y - mu)*rstd*wv + bv, 0.f);
    *(float4*)&out[i] = v;
}

// ---------------- launch -----------------------------------------------------
extern "C" void kernel_launch(void* const* d_in, const int* in_sizes, int n_in,
                              void* d_out, int out_size)
{
    const float* x   = (const float*)d_in[0];
    const float* tw  = (const float*)d_in[1];
    const float* tb  = (const float*)d_in[2];
    const float* pw  = (const float*)d_in[3];
    const float* pb  = (const float*)d_in[4];
    const float* gw  = (const float*)d_in[5];
    const float* gb  = (const float*)d_in[6];
    const float* rw  = (const float*)d_in[7];
    const float* rb  = (const float*)d_in[8];
    const float* gnw = (const float*)d_in[9];
    const float* gnb = (const float*)d_in[10];
    const float* bnw = (const float*)d_in[11];
    const float* bnb = (const float*)d_in[12];
    float* out = (float*)d_out;

    wtrans_kernel<<<96, 256>>>(tw, pw, gw, rw);

    for (int layer = 0; layer < 2; layer++) {
        proj_kernel<<<dim3(SP/64, Bb), 256>>>(layer, x, tb, pb, gb);
        attn01_kernel<<<dim3(Bb*Sd*Sd, 2), 192>>>();
        attn2_kernel<<<Bb*Sd*Sd, 192>>>(rb);
        gnres_kernel<<<dim3(4, Cc, Bb), 256>>>(layer, x, gnw + layer*Cc, gnb + layer*Cc,
                                               layer == 1 ? 1 : 0);
    }
    bnapply_kernel<<<((Bb*Cc*SP/4) + 255)/256, 256>>>(bnw, bnb, out);
}

// round 17
// speedup vs baseline: 1.2585x; 1.2585x over previous
#include <cuda_runtime.h>
#include <cuda_fp16.h>

#define Sd 48
#define SP (Sd*Sd*Sd)      // 110592
#define Bb 2
#define Cc 128
#define NVx (Bb*SP)        // 221184

// ---------------- mma / ldmatrix / cp.async helpers -------------------------
__device__ __forceinline__ void mma_f16(float* d, const unsigned* a, const unsigned* b) {
    asm volatile(
        "mma.sync.aligned.m16n8k16.row.col.f32.f16.f16.f32 "
        "{%0,%1,%2,%3},{%4,%5,%6,%7},{%8,%9},{%0,%1,%2,%3};"
        : "+f"(d[0]), "+f"(d[1]), "+f"(d[2]), "+f"(d[3])
        : "r"(a[0]), "r"(a[1]), "r"(a[2]), "r"(a[3]), "r"(b[0]), "r"(b[1]));
}
__device__ __forceinline__ unsigned smaddr(const void* p) {
    unsigned a;
    asm("{ .reg .u64 t; cvta.to.shared.u64 t, %1; cvt.u32.u64 %0, t; }" : "=r"(a) : "l"(p));
    return a;
}
__device__ __forceinline__ void ldsm_x4(unsigned* r, unsigned a) {
    asm volatile("ldmatrix.sync.aligned.m8n8.x4.shared.b16 {%0,%1,%2,%3},[%4];"
        : "=r"(r[0]), "=r"(r[1]), "=r"(r[2]), "=r"(r[3]) : "r"(a));
}
__device__ __forceinline__ void ldsm_x2(unsigned* r, unsigned a) {
    asm volatile("ldmatrix.sync.aligned.m8n8.x2.shared.b16 {%0,%1},[%2];"
        : "=r"(r[0]), "=r"(r[1]) : "r"(a));
}
__device__ __forceinline__ void ldsm_x4_t(unsigned* r, unsigned a) {
    asm volatile("ldmatrix.sync.aligned.m8n8.x4.trans.shared.b16 {%0,%1,%2,%3},[%4];"
        : "=r"(r[0]), "=r"(r[1]), "=r"(r[2]), "=r"(r[3]) : "r"(a));
}
__device__ __forceinline__ float2 h2f2(unsigned u) {
    __half2 h = *reinterpret_cast<__half2*>(&u);
    return __half22float2(h);
}
__device__ __forceinline__ void cpa16(void* smem, const void* gmem) {
    unsigned s = smaddr(smem);
    asm volatile("cp.async.cg.shared.global [%0], [%1], 16;" :: "r"(s), "l"(gmem));
}
#define CPA_COMMIT() asm volatile("cp.async.commit_group;")
#define CPA_WAIT0()  asm volatile("cp.async.wait_group 0;")

// ---------------- scratch --------------------------------------------------
__device__ __half g_hh[(size_t)Bb*Cc*SP];      // residual stream h (fp16)
__device__ __half g_T[(size_t)NVx*64];
__device__ __half g_P[(size_t)NVx*64];
__device__ __half g_G[(size_t)NVx*64];
__device__ __half g_Yd[(size_t)NVx*64];        // D-dir partial, vox-major
__device__ __half g_Yh[(size_t)NVx*64];        // H-dir partial, vox-major
__device__ __half g_Yw[(size_t)NVx*64];        // final combined Y, g-major
__device__ float g_md[NVx]; __device__ float g_sd[NVx];
__device__ float g_mh[NVx]; __device__ float g_sh[NVx];
__device__ __half g_cross[(size_t)Bb*Cc*SP];   // channel-first, fp16
__device__ __half g_WT16[192*128];             // fused theta/phi/G weights [m][k]
__device__ __half g_rwT16[128*64];             // r_w [m=ch][k=g]
__device__ float g_gnsum[Bb*32]; __device__ float g_gnss[Bb*32];
__device__ float g_bnsum[Cc];    __device__ float g_bnss[Cc];

// ---------------- one-time weight convert + BN-stat zero --------------------
__global__ __launch_bounds__(256) void wtrans_kernel(
    const float* __restrict__ tw, const float* __restrict__ pw,
    const float* __restrict__ gw, const float* __restrict__ rw)
{
    int idx = blockIdx.x*256 + threadIdx.x;
    if (idx < 192*128) {
        float v;
        if (idx < 64*128)       v = tw[idx];
        else if (idx < 128*128) v = pw[idx - 64*128];
        else                    v = gw[idx - 128*128];
        g_WT16[idx] = __float2half(v);
    }
    if (idx < 128*64) g_rwT16[idx] = __float2half(rw[idx]);
    if (idx < Cc) { g_bnsum[idx] = 0.f; g_bnss[idx] = 0.f; }
}

// ---------------- projection (fp16 mma): [192m x 64n] tile, K=128 ----------
__global__ __launch_bounds__(256) void proj_kernel(
    int layer, const float* __restrict__ x,
    const float* __restrict__ tb, const float* __restrict__ pb,
    const float* __restrict__ gb)
{
    __shared__ __align__(16) __half SM[192*40*2 + 32*72];
    __half* As0 = SM;                  // [192][40]
    __half* As1 = SM + 192*40;
    __half* Bs  = SM + 192*40*2;       // [32][72]
    __half* U   = SM;                  // staging [vox 64][m 200] (aliases As)
    const int b = blockIdx.y, n0 = blockIdx.x*64, tid = threadIdx.x;
    if (blockIdx.x == 0 && blockIdx.y == 0 && tid < Bb*32) {
        g_gnsum[tid] = 0.f; g_gnss[tid] = 0.f;
    }
    const int warp = tid >> 5, lane = tid & 31;
    const int grp = lane >> 2, tig = lane & 3;
    const int m_base = (warp >> 1) * 48, n_base = (warp & 1) * 32;

    float acc[3][4][4];
    #pragma unroll
    for (int mt = 0; mt < 3; mt++)
        #pragma unroll
        for (int nt = 0; nt < 4; nt++)
            #pragma unroll
            for (int q = 0; q < 4; q++) acc[mt][nt][q] = 0.f;

    const unsigned A0addr = smaddr(&As0[(m_base + (lane & 15))*40 + (lane >> 4)*8]);
    const unsigned Baddr  = smaddr(&Bs[((lane & 7) + ((lane >> 3) & 1)*8)*72
                                       + n_base + (lane >> 4)*8]);

    #pragma unroll
    for (int it = 0; it < 3; it++) {
        int idx = it*256 + tid;
        int m = idx >> 2, kp = (idx & 3)*8;
        cpa16(&As0[m*40 + kp], &g_WT16[m*128 + kp]);
    }
    CPA_COMMIT();

    for (int k0 = 0; k0 < 128; k0 += 32) {
        const int buf = (k0 >> 5) & 1;
        {
            int kk = tid >> 3, n8 = (tid & 7)*8;
            size_t off = (size_t)(b*Cc + k0 + kk)*SP + n0 + n8;
            if (layer) {
                *(uint4*)&Bs[kk*72 + n8] = *(const uint4*)&g_hh[off];
            } else {
                const float* s = &x[off];
                float4 v0 = *(const float4*)s, v1 = *(const float4*)(s + 4);
                __half2 h0 = __floats2half2_rn(v0.x, v0.y);
                __half2 h1 = __floats2half2_rn(v0.z, v0.w);
                __half2 h2 = __floats2half2_rn(v1.x, v1.y);
                __half2 h3 = __floats2half2_rn(v1.z, v1.w);
                uint4 pk;
                pk.x = *(unsigned*)&h0; pk.y = *(unsigned*)&h1;
                pk.z = *(unsigned*)&h2; pk.w = *(unsigned*)&h3;
                *(uint4*)&Bs[kk*72 + n8] = pk;
            }
        }
        CPA_WAIT0();
        __syncthreads();
        if (k0 + 32 < 128) {
            __half* Anext = buf ? As0 : As1;
            #pragma unroll
            for (int it = 0; it < 3; it++) {
                int idx = it*256 + tid;
                int m = idx >> 2, kp = (idx & 3)*8;
                cpa16(&Anext[m*40 + kp], &g_WT16[m*128 + k0 + 32 + kp]);
            }
            CPA_COMMIT();
        }
        const unsigned Aaddr = A0addr + (buf ? 192*40*2 : 0);
        #pragma unroll
        for (int kc = 0; kc < 2; kc++) {
            unsigned bv0[4], bv1[4];
            ldsm_x4_t(bv0, Baddr + kc*16*144);
            ldsm_x4_t(bv1, Baddr + kc*16*144 + 32);
            #pragma unroll
            for (int mt = 0; mt < 3; mt++) {
                unsigned af[4];
                ldsm_x4(af, Aaddr + mt*16*80 + kc*32);
                mma_f16(acc[mt][0], af, bv0);
                mma_f16(acc[mt][1], af, bv0 + 2);
                mma_f16(acc[mt][2], af, bv1);
                mma_f16(acc[mt][3], af, bv1 + 2);
            }
        }
        __syncthreads();
    }

    #pragma unroll
    for (int mt = 0; mt < 3; mt++) {
        #pragma unroll
        for (int rr = 0; rr < 2; rr++) {
            const int r = m_base + mt*16 + rr*8 + grp;
            const float bv = (r < 64) ? tb[r] : (r < 128 ? pb[r-64] : gb[r-128]);
            #pragma unroll
            for (int nt = 0; nt < 4; nt++) {
                const int c = n_base + nt*8 + tig*2;
                U[ c   *200 + r] = __float2half(acc[mt][nt][rr*2 + 0] + bv);
                U[(c+1)*200 + r] = __float2half(acc[mt][nt][rr*2 + 1] + bv);
            }
        }
    }
    __syncthreads();
    #pragma unroll
    for (int it = 0; it < 6; it++) {
        int idx = it*256 + tid;               // 0..1535
        int seg = idx >> 9;                   // 0:T 1:P 2:G
        int rem = idx & 511;
        int vox = rem >> 3, ch = rem & 7;
        __half* dst = (seg == 0) ? g_T : ((seg == 1) ? g_P : g_G);
        uint4 val = *(const uint4*)&U[vox*200 + seg*64 + ch*8];
        *(uint4*)&dst[((size_t)b*SP + n0 + vox)*64 + ch*8] = val;
    }
}

// ---------------- merged D/H attention (blockIdx.y = direction 0/1) --------
__global__ __launch_bounds__(192) void attn01_kernel() {
    __shared__ __half Tl[48*72];
    __shared__ __half Pl[48*72];
    __shared__ __half Gl[48*72];
    __shared__ __half Sh[48*72];

    const int DIR = blockIdx.y;
    const int pid = blockIdx.x;
    const int b = pid / (Sd*Sd);
    const int rr = pid % (Sd*Sd);
    const int u = rr / Sd, v = rr % Sd;
    size_t base; int stride;
    if (DIR == 0) { base = (size_t)b*SP + u*Sd + v;    stride = Sd*Sd; }
    else          { base = (size_t)b*SP + u*Sd*Sd + v; stride = Sd;    }
    const int tid = threadIdx.x;
    const int warp = tid >> 5, lane = tid & 31;
    const int grp = lane >> 2, tig = lane & 3;

    for (int l = tid; l < 48*8; l += 192) {
        int i = l >> 3, k8 = (l & 7) * 8;
        size_t o = (base + (size_t)i*stride)*64 + k8;
        cpa16(&Gl[i*72 + k8], &g_G[o]);          // async; needed only for AV
        *(uint4*)&Tl[i*72 + k8] = *(const uint4*)&g_T[o];
        *(uint4*)&Pl[i*72 + k8] = *(const uint4*)&g_P[o];
    }
    CPA_COMMIT();
    __syncthreads();

    const int mrow0 = (warp >> 1) * 16;
    const int mr = mrow0 + grp;
    const int nhalf = (warp & 1) * 24;
    const int ncol0 = (warp & 1) * 32;

    const unsigned Ta = smaddr(&Tl[(mrow0 + (lane & 15))*72 + (lane >> 4)*8]);
    const unsigned Pa = smaddr(&Pl[(nhalf + (lane & 7))*72 + ((lane >> 3) & 1)*8]);
    const unsigned Ga = smaddr(&Gl[((lane & 7) + ((lane >> 3) & 1)*8)*72
                                   + ncol0 + (lane >> 4)*8]);

    float sacc[3][4];
    #pragma unroll
    for (int nt = 0; nt < 3; nt++)
        #pragma unroll
        for (int q = 0; q < 4; q++) sacc[nt][q] = 0.f;
    #pragma unroll
    for (int kc = 0; kc < 4; kc++) {
        unsigned af[4];
        ldsm_x4(af, Ta + kc*32);
        #pragma unroll
        for (int nt = 0; nt < 3; nt++) {
            unsigned bf[2];
            ldsm_x2(bf, Pa + nt*8*144 + kc*32);
            mma_f16(sacc[nt], af, bf);
        }
    }

    #pragma unroll
    for (int nt = 0; nt < 3; nt++) {
        const int j0 = nhalf + nt*8 + tig*2;
        float c0 = sacc[nt][0], c1 = sacc[nt][1], c2 = sacc[nt][2], c3 = sacc[nt][3];
        if (DIR != 0) {
            if (mr     == j0    ) c0 = -1e30f;
            if (mr     == j0 + 1) c1 = -1e30f;
            if (mr + 8 == j0    ) c2 = -1e30f;
            if (mr + 8 == j0 + 1) c3 = -1e30f;
        }
        *(__half2*)&Sh[ mr     *72 + j0] = __floats2half2_rn(c0, c1);
        *(__half2*)&Sh[(mr + 8)*72 + j0] = __floats2half2_rn(c2, c3);
    }
    __syncthreads();

    {
        const int r = tid >> 2, q = tid & 3;
        float vals[12];
        float mx = -3.0e38f;
        #pragma unroll
        for (int j = 0; j < 12; j += 2) {
            float2 vv = h2f2(*(const unsigned*)&Sh[r*72 + q*12 + j]);
            vals[j] = vv.x; vals[j+1] = vv.y;
            mx = fmaxf(mx, fmaxf(vv.x, vv.y));
        }
        mx = fmaxf(mx, __shfl_xor_sync(0xffffffffu, mx, 1));
        mx = fmaxf(mx, __shfl_xor_sync(0xffffffffu, mx, 2));
        float sm = 0.f;
        #pragma unroll
        for (int j = 0; j < 12; j++) {
            float e = __expf(vals[j] - mx);
            sm += e;
            Tl[r*72 + q*12 + j] = __float2half(e);
        }
        sm += __shfl_xor_sync(0xffffffffu, sm, 1);
        sm += __shfl_xor_sync(0xffffffffu, sm, 2);
        if (q == 0) {
            size_t vx = base + (size_t)r*stride;
            if (DIR == 0) { g_md[vx] = mx; g_sd[vx] = sm; }
            else          { g_mh[vx] = mx; g_sh[vx] = sm; }
        }
    }
    CPA_WAIT0();             // G tile now required
    __syncthreads();

    float yacc[4][4];
    #pragma unroll
    for (int nt = 0; nt < 4; nt++)
        #pragma unroll
        for (int q = 0; q < 4; q++) yacc[nt][q] = 0.f;
    #pragma unroll
    for (int kc = 0; kc < 3; kc++) {
        unsigned af[4];
        ldsm_x4(af, Ta + kc*32);
        #pragma unroll
        for (int pair = 0; pair < 2; pair++) {
            unsigned bv[4];
            ldsm_x4_t(bv, Ga + kc*16*144 + pair*32);
            mma_f16(yacc[pair*2],     af, bv);
            mma_f16(yacc[pair*2 + 1], af, bv + 2);
        }
    }

    __half* Yout = (DIR == 0) ? g_Yd : g_Yh;
    #pragma unroll
    for (int nt = 0; nt < 4; nt++) {
        const int c = ncol0 + nt*8 + tig*2;
        *(__half2*)&Yout[(base + (size_t)mr*stride)*64 + c] =
            __floats2half2_rn(yacc[nt][0], yacc[nt][1]);
        *(__half2*)&Yout[(base + (size_t)(mr + 8)*stride)*64 + c] =
            __floats2half2_rn(yacc[nt][2], yacc[nt][3]);
    }
}

// ---------------- W-direction attention + fused 3-way combine ---------------
__global__ __launch_bounds__(192) void attn2_kernel() {
    __shared__ __half Tl[48*72];
    __shared__ __half Pl[48*72];
    __shared__ __half Gl[48*72];
    __shared__ __half Sh[48*72];
    __shared__ float  rmS[48], rsS[48];

    const int pid = blockIdx.x;
    const int b = pid / (Sd*Sd);
    const int rr = pid % (Sd*Sd);
    const int u = rr / Sd, v = rr % Sd;
    const size_t base = (size_t)b*SP + u*Sd*Sd + v*Sd;   // stride 1
    const int tid = threadIdx.x;
    const int warp = tid >> 5, lane = tid & 31;
    const int grp = lane >> 2, tig = lane & 3;

    for (int l = tid; l < 48*8; l += 192) {
        int i = l >> 3, k8 = (l & 7) * 8;
        size_t o = (base + (size_t)i)*64 + k8;
        cpa16(&Gl[i*72 + k8], &g_G[o]);
        *(uint4*)&Tl[i*72 + k8] = *(const uint4*)&g_T[o];
        *(uint4*)&Pl[i*72 + k8] = *(const uint4*)&g_P[o];
    }
    CPA_COMMIT();
    __syncthreads();

    const int mrow0 = (warp >> 1) * 16;
    const int mr = mrow0 + grp;
    const int nhalf = (warp & 1) * 24;
    const int ncol0 = (warp & 1) * 32;

    const unsigned Ta = smaddr(&Tl[(mrow0 + (lane & 15))*72 + (lane >> 4)*8]);
    const unsigned Pa = smaddr(&Pl[(nhalf + (lane & 7))*72 + ((lane >> 3) & 1)*8]);
    const unsigned Ga = smaddr(&Gl[((lane & 7) + ((lane >> 3) & 1)*8)*72
                                   + ncol0 + (lane >> 4)*8]);

    float sacc[3][4];
    #pragma unroll
    for (int nt = 0; nt < 3; nt++)
        #pragma unroll
        for (int q = 0; q < 4; q++) sacc[nt][q] = 0.f;
    #pragma unroll
    for (int kc = 0; kc < 4; kc++) {
        unsigned af[4];
        ldsm_x4(af, Ta + kc*32);
        #pragma unroll
        for (int nt = 0; nt < 3; nt++) {
            unsigned bf[2];
            ldsm_x2(bf, Pa + nt*8*144 + kc*32);
            mma_f16(sacc[nt], af, bf);
        }
    }

    #pragma unroll
    for (int nt = 0; nt < 3; nt++) {
        const int j0 = nhalf + nt*8 + tig*2;
        float c0 = sacc[nt][0], c1 = sacc[nt][1], c2 = sacc[nt][2], c3 = sacc[nt][3];
        if (mr     == j0    ) c0 = -1e30f;
        if (mr     == j0 + 1) c1 = -1e30f;
        if (mr + 8 == j0    ) c2 = -1e30f;
        if (mr + 8 == j0 + 1) c3 = -1e30f;
        *(__half2*)&Sh[ mr     *72 + j0] = __floats2half2_rn(c0, c1);
        *(__half2*)&Sh[(mr + 8)*72 + j0] = __floats2half2_rn(c2, c3);
    }
    __syncthreads();

    {
        const int r = tid >> 2, q = tid & 3;
        float vals[12];
        float mx = -3.0e38f;
        #pragma unroll
        for (int j = 0; j < 12; j += 2) {
            float2 vv = h2f2(*(const unsigned*)&Sh[r*72 + q*12 + j]);
            vals[j] = vv.x; vals[j+1] = vv.y;
            mx = fmaxf(mx, fmaxf(vv.x, vv.y));
        }
        mx = fmaxf(mx, __shfl_xor_sync(0xffffffffu, mx, 1));
        mx = fmaxf(mx, __shfl_xor_sync(0xffffffffu, mx, 2));
        float sm = 0.f;
        #pragma unroll
        for (int j = 0; j < 12; j++) {
            float e = __expf(vals[j] - mx);
            sm += e;
            Tl[r*72 + q*12 + j] = __float2half(e);
        }
        sm += __shfl_xor_sync(0xffffffffu, sm, 1);
        sm += __shfl_xor_sync(0xffffffffu, sm, 2);
        if (q == 0) { rmS[r] = mx; rsS[r] = sm; }
    }
    CPA_WAIT0();
    __syncthreads();

    float yacc[4][4];
    #pragma unroll
    for (int nt = 0; nt < 4; nt++)
        #pragma unroll
        for (int q = 0; q < 4; q++) yacc[nt][q] = 0.f;
    #pragma unroll
    for (int kc = 0; kc < 3; kc++) {
        unsigned af[4];
        ldsm_x4(af, Ta + kc*32);
        #pragma unroll
        for (int pair = 0; pair < 2; pair++) {
            unsigned bv[4];
            ldsm_x4_t(bv, Ga + kc*16*144 + pair*32);
            mma_f16(yacc[pair*2],     af, bv);
            mma_f16(yacc[pair*2 + 1], af, bv + 2);
        }
    }

    #pragma unroll
    for (int nt = 0; nt < 4; nt++) {
        const int c = ncol0 + nt*8 + tig*2;
        *(__half2*)&Sh[ mr     *72 + c] = __floats2half2_rn(yacc[nt][0], yacc[nt][1]);
        *(__half2*)&Sh[(mr + 8)*72 + c] = __floats2half2_rn(yacc[nt][2], yacc[nt][3]);
    }
    __syncthreads();

    // fused 3-way combine: thread = (voxel pair, 8 g-values); half2 g-major out
    {
        const int ip = tid >> 3;
        const int g0 = (tid & 7) * 8;
        const int i0 = ip*2, i1 = i0 + 1;
        const size_t vox0 = base + i0, vox1 = base + i1;

        float md0 = g_md[vox0], sd0 = g_sd[vox0];
        float mh0 = g_mh[vox0], sh0 = g_sh[vox0];
        float mw0 = rmS[i0],    sw0 = rsS[i0];
        float m0  = fmaxf(md0, fmaxf(mh0, mw0));
        float wd0 = __expf(md0 - m0), wh0 = __expf(mh0 - m0), ww0 = __expf(mw0 - m0);
        float iv0 = 1.0f / (sd0*wd0 + sh0*wh0 + sw0*ww0);
        wd0 *= iv0; wh0 *= iv0; ww0 *= iv0;

        float md1 = g_md[vox1], sd1 = g_sd[vox1];
        float mh1 = g_mh[vox1], sh1 = g_sh[vox1];
        float mw1 = rmS[i1],    sw1 = rsS[i1];
        float m1  = fmaxf(md1, fmaxf(mh1, mw1));
        float wd1 = __expf(md1 - m1), wh1 = __expf(mh1 - m1), ww1 = __expf(mw1 - m1);
        float iv1 = 1.0f / (sd1*wd1 + sh1*wh1 + sw1*ww1);
        wd1 *= iv1; wh1 *= iv1; ww1 *= iv1;

        uint4 a0u = *(const uint4*)&g_Yd[vox0*64 + g0];
        uint4 a1u = *(const uint4*)&g_Yd[vox1*64 + g0];
        uint4 h0u = *(const uint4*)&g_Yh[vox0*64 + g0];
        uint4 h1u = *(const uint4*)&g_Yh[vox1*64 + g0];
        uint4 y0u = *(const uint4*)&Sh[i0*72 + g0];
        uint4 y1u = *(const uint4*)&Sh[i1*72 + g0];
        const unsigned* a0 = (const unsigned*)&a0u;
        const unsigned* a1 = (const unsigned*)&a1u;
        const unsigned* h0 = (const unsigned*)&h0u;
        const unsigned* h1 = (const unsigned*)&h1u;
        const unsigned* y0 = (const unsigned*)&y0u;
        const unsigned* y1 = (const unsigned*)&y1u;

        const size_t sp0 = base - (size_t)b*SP;
        #pragma unroll
        for (int q = 0; q < 4; q++) {
            float2 av0 = h2f2(a0[q]), hv0 = h2f2(h0[q]), yv0 = h2f2(y0[q]);
            float2 av1 = h2f2(a1[q]), hv1 = h2f2(h1[q]), yv1 = h2f2(y1[q]);
            float o0a = av0.x*wd0 + hv0.x*wh0 + yv0.x*ww0;
            float o0b = av0.y*wd0 + hv0.y*wh0 + yv0.y*ww0;
            float o1a = av1.x*wd1 + hv1.x*wh1 + yv1.x*ww1;
            float o1b = av1.y*wd1 + hv1.y*wh1 + yv1.y*ww1;
            int g = g0 + q*2;
            *(__half2*)&g_Yw[((size_t)(b*64 + g    ))*SP + sp0 + i0] =
                __floats2half2_rn(o0a, o1a);
            *(__half2*)&g_Yw[((size_t)(b*64 + g + 1))*SP + sp0 + i0] =
                __floats2half2_rn(o0b, o1b);
        }
    }
}

// ---------------- cross GEMM (fp16 mma): [128ch x 64vox], K=64 + GN sums ---
__global__ __launch_bounds__(256) void cross_kernel(const float* __restrict__ rb)
{
    __shared__ __half As[128*72];   // rw [m=ch][k=g] -> output staging [ch][vox]
    __shared__ __half Bs[64*72];    // Y  [k=g 64][n]
    __shared__ float gsum[32], gss[32];
    const int b = blockIdx.y, n0 = blockIdx.x*64, tid = threadIdx.x;
    const int warp = tid >> 5, lane = tid & 31;
    const int grp = lane >> 2, tig = lane & 3;
    const int m_base = (warp >> 1) * 32, n_base = (warp & 1) * 32;

    float acc[2][4][4];
    #pragma unroll
    for (int mt = 0; mt < 2; mt++)
        #pragma unroll
        for (int nt = 0; nt < 4; nt++)
            #pragma unroll
            for (int q = 0; q < 4; q++) acc[mt][nt][q] = 0.f;

    #pragma unroll
    for (int it = 0; it < 4; it++) {
        int idx = it*256 + tid;
        int m = idx >> 3, kp = (idx & 7)*8;
        *(uint4*)&As[m*72 + kp] = *(const uint4*)&g_rwT16[m*64 + kp];
    }
    #pragma unroll
    for (int it = 0; it < 2; it++) {
        int idx = it*256 + tid;                 // 0..511
        int kk = idx >> 3, n8 = (idx & 7)*8;
        *(uint4*)&Bs[kk*72 + n8] =
            *(const uint4*)&g_Yw[((size_t)b*64 + kk)*SP + n0 + n8];
    }
    if (tid < 32) { gsum[tid] = 0.f; gss[tid] = 0.f; }

    const unsigned Aaddr = smaddr(&As[(m_base + (lane & 15))*72 + (lane >> 4)*8]);
    const unsigned Baddr = smaddr(&Bs[((lane & 7) + ((lane >> 3) & 1)*8)*72
                                      + n_base + (lane >> 4)*8]);
    __syncthreads();

    #pragma unroll
    for (int kk = 0; kk < 4; kk++) {
        unsigned bv0[4], bv1[4];
        ldsm_x4_t(bv0, Baddr + kk*16*144);
        ldsm_x4_t(bv1, Baddr + kk*16*144 + 32);
        #pragma unroll
        for (int mt = 0; mt < 2; mt++) {
            unsigned af[4];
            ldsm_x4(af, Aaddr + mt*16*144 + kk*32);
            mma_f16(acc[mt][0], af, bv0);
            mma_f16(acc[mt][1], af, bv0 + 2);
            mma_f16(acc[mt][2], af, bv1);
            mma_f16(acc[mt][3], af, bv1 + 2);
        }
    }
    __syncthreads();

    #pragma unroll
    for (int mt = 0; mt < 2; mt++) {
        #pragma unroll
        for (int rr = 0; rr < 2; rr++) {
            const int r = m_base + mt*16 + rr*8 + grp;
            const float bv = rb[r];
            float ps = 0.f, pss = 0.f;
            #pragma unroll
            for (int nt = 0; nt < 4; nt++) {
                const int c = n_base + nt*8 + tig*2;
                float v0 = acc[mt][nt][rr*2 + 0] + bv;
                float v1 = acc[mt][nt][rr*2 + 1] + bv;
                *(__half2*)&As[r*72 + c] = __floats2half2_rn(v0, v1);
                ps += v0 + v1; pss += v0*v0 + v1*v1;
            }
            ps  += __shfl_xor_sync(0xffffffffu, ps, 1);
            ps  += __shfl_xor_sync(0xffffffffu, ps, 2);
            pss += __shfl_xor_sync(0xffffffffu, pss, 1);
            pss += __shfl_xor_sync(0xffffffffu, pss, 2);
            if (tig == 0) {
                atomicAdd(&gsum[r >> 2], ps);
                atomicAdd(&gss [r >> 2], pss);
            }
        }
    }
    __syncthreads();
    #pragma unroll
    for (int it = 0; it < 4; it++) {
        int idx = it*256 + tid;               // 0..1023
        int r = idx >> 3, ch = idx & 7;
        *(uint4*)&g_cross[((size_t)b*Cc + r)*SP + n0 + ch*8] =
            *(const uint4*)&As[r*72 + ch*8];
    }
    if (tid < 32) {
        atomicAdd(&g_gnsum[b*32 + tid], gsum[tid]);
        atomicAdd(&g_gnss [b*32 + tid], gss[tid]);
    }
}

// ---------------- GroupNorm + residual (streaming, channel-first) ----------
__global__ __launch_bounds__(256) void gnres_kernel(
    int layer, const float* __restrict__ x,
    const float* __restrict__ gnw, const float* __restrict__ gnb,
    int accum_bn)
{
    const int c = blockIdx.y, b = blockIdx.z, chunk = blockIdx.x;
    const size_t base = ((size_t)(b*Cc + c))*SP + (size_t)chunk*(SP/4);
    const int g = c >> 2;
    const float invN = 1.0f / (4.0f * SP);
    float mu  = g_gnsum[b*32 + g] * invN;
    float var = g_gnss[b*32 + g] * invN - mu*mu;
    float rstd = rsqrtf(var + 1e-5f);
    float w = gnw[c], bias = gnb[c];
    float s = 0.f, ss = 0.f;
    for (int j = 0; j < 27; j++) {
        size_t o = base + (size_t)j*1024 + threadIdx.x*4;
        uint2 ch = *(const uint2*)&g_cross[o];
        float2 c01 = h2f2(ch.x), c23 = h2f2(ch.y);
        float4 rv;
        if (layer) {
            uint2 hv = *(const uint2*)&g_hh[o];
            float2 r01 = h2f2(hv.x), r23 = h2f2(hv.y);
            rv.x = r01.x; rv.y = r01.y; rv.z = r23.x; rv.w = r23.y;
        } else {
            rv = *(const float4*)&x[o];
        }
        float4 h;
        h.x = rv.x + (c01.x - mu)*rstd*w + bias;
        h.y = rv.y + (c01.y - mu)*rstd*w + bias;
        h.z = rv.z + (c23.x - mu)*rstd*w + bias;
        h.w = rv.w + (c23.y - mu)*rstd*w + bias;
        uint2 hw;
        __half2 w0 = __floats2half2_rn(h.x, h.y);
        __half2 w1 = __floats2half2_rn(h.z, h.w);
        hw.x = *(unsigned*)&w0; hw.y = *(unsigned*)&w1;
        *(uint2*)&g_hh[o] = hw;
        if (accum_bn) {
            s  += h.x + h.y + h.z + h.w;
            ss += h.x*h.x + h.y*h.y + h.z*h.z + h.w*h.w;
        }
    }
    if (accum_bn) {
        #pragma unroll
        for (int o = 16; o > 0; o >>= 1) {
            s  += __shfl_xor_sync(0xffffffffu, s,  o);
            ss += __shfl_xor_sync(0xffffffffu, ss, o);
        }
        __shared__ float ws[8], wss[8];
        int wid = threadIdx.x >> 5, lane = threadIdx.x & 31;
        if (lane == 0) { ws[wid] = s; wss[wid] = ss; }
        __syncthreads();
        if (threadIdx.x == 0) {
            float ts = 0.f, tss = 0.f;
            #pragma unroll
            for (int k = 0; k < 8; k++) { ts += ws[k]; tss += wss[k]; }
            atomicAdd(&g_bnsum[c], ts);
            atomicAdd(&g_bnss[c],  tss);
        }
    }
}

// ---------------- BatchNorm apply + ReLU ------------------------------------
__global__ __launch_bounds__(256) void bnapply_kernel(
    const float* __restrict__ bw, const float* __restrict__ bb, float* __restrict__ out)
{
    size_t i4 = (size_t)blockIdx.x*256 + threadIdx.x;
    if (i4 >= (size_t)Bb*Cc*SP/4) return;
    size_t i = i4 * 4;
    int c = (int)((i / SP) & 127);
    const float invN = 1.0f / ((float)Bb * SP);
    float mu  = g_bnsum[c] * invN;
    float var = g_bnss[c] * invN - mu*mu;
    float rstd = rsqrtf(var + 1e-5f);
    float wv = bw[c], bv = bb[c];
    uint2 hv = *(const uint2*)&g_hh[i];
    float2 v01 = h2f2(hv.x), v23 = h2f2(hv.y);
    float4 v;
    v.x = fmaxf((v01.x - mu)*rstd*wv + bv, 0.f);
    v.y = fmaxf((v01.y - mu)*rstd*wv + bv, 0.f);
    v.z = fmaxf((v23.x - mu)*rstd*wv + bv, 0.f);
    v.w = fmaxf((v23.y - mu)*rstd*wv + bv, 0.f);
    *(float4*)&out[i] = v;
}

// ---------------- launch -----------------------------------------------------
extern "C" void kernel_launch(void* const* d_in, const int* in_sizes, int n_in,
                              void* d_out, int out_size)
{
    const float* x   = (const float*)d_in[0];
    const float* tw  = (const float*)d_in[1];
    const float* tb  = (const float*)d_in[2];
    const float* pw  = (const float*)d_in[3];
    const float* pb  = (const float*)d_in[4];
    const float* gw  = (const float*)d_in[5];
    const float* gb  = (const float*)d_in[6];
    const float* rw  = (const float*)d_in[7];
    const float* rb  = (const float*)d_in[8];
    const float* gnw = (const float*)d_in[9];
    const float* gnb = (const float*)d_in[10];
    const float* bnw = (const float*)d_in[11];
    const float* bnb = (const float*)d_in[12];
    float* out = (float*)d_out;

    wtrans_kernel<<<96, 256>>>(tw, pw, gw, rw);

    for (int layer = 0; layer < 2; layer++) {
        proj_kernel<<<dim3(SP/64, Bb), 256>>>(layer, x, tb, pb, gb);
        attn01_kernel<<<dim3(Bb*Sd*Sd, 2), 192>>>();
        attn2_kernel<<<Bb*Sd*Sd, 192>>>();
        cross_kernel<<<dim3(SP/64, Bb), 256>>>(rb);
        gnres_kernel<<<dim3(4, Cc, Bb), 256>>>(layer, x, gnw + layer*Cc, gnb + layer*Cc,
                                               layer == 1 ? 1 : 0);
    }
    bnapply_kernel<<<((Bb*Cc*SP/4) + 255)/256, 256>>>(bnw, bnb, out);
}